// round 13
// baseline (speedup 1.0000x reference)
#include <cuda_runtime.h>
#include <cuda_fp16.h>
#include <math.h>
#include <stdint.h>

#define NB 8
#define NL 48
#define NT 512
#define HD 128
#define NG 10
#define M_TOTAL (NB*NL*NT)          // 196608

#define OFF_PI  0
#define OFF_SIG (M_TOTAL*NG)
#define OFF_MU  (2*M_TOTAL*NG)
#define OFF_D   (3*M_TOTAL*NG)
#define OFF_CB  (3*M_TOTAL*NG + M_TOTAL)

// scratch (device globals: no allocation)
__device__ float g_Al[NB*NL*HD];    // 384 x 128
__device__ float g_At[NB*NT*HD];    // 4096 x 128
__device__ uint2 g_Wfrag[1024];     // fp16 W fragments [kc 8][nc 4][lane 32]

__device__ __forceinline__ float elu1(float x) {
    return x > 0.0f ? x : (__expf(x) - 1.0f);
}

// pack two fp32 into f16x2: {lo16 = e0, hi16 = e1}
__device__ __forceinline__ uint32_t cvt2h(float e0, float e1) {
    uint32_t r;
    asm("cvt.rn.f16x2.f32 %0, %1, %2;" : "=r"(r) : "f"(e1), "f"(e0));
    return r;
}

// warp-level fp16 MMA, d += a*b, fp32 accumulate (baseline PTX sm_80+)
__device__ __forceinline__ void mma_f16(float* d, const uint32_t* a, const uint32_t* b) {
    asm volatile("mma.sync.aligned.m16n8k16.row.col.f32.f16.f16.f32 "
        "{%0,%1,%2,%3}, {%4,%5,%6,%7}, {%8,%9}, {%0,%1,%2,%3};"
        : "+f"(d[0]), "+f"(d[1]), "+f"(d[2]), "+f"(d[3])
        : "r"(a[0]), "r"(a[1]), "r"(a[2]), "r"(a[3]), "r"(b[0]), "r"(b[1]));
}

__device__ __forceinline__ float wval(int n, int k, const float* __restrict__ wp,
                                      const float* __restrict__ ws,
                                      const float* __restrict__ wm) {
    if (n < 10) return wp[n*HD + k];
    if (n < 20) return ws[(n-10)*HD + k];
    if (n < 30) return wm[(n-20)*HD + k];
    return 0.0f;
}

// ---------------------------------------------------------------------------
// Precompute: A_l = s*(lig_s@W1^T + b1 - mean) + beta ;  A_t = s*(pro_s@W1^T)
// Last block additionally converts head weights to fp16 MMA B-fragments.
// ---------------------------------------------------------------------------
#define PRE_ROWS 32
#define PRE_THREADS 512
#define XS_P  129
#define W1T_P 132
#define PRE_SMEM ((PRE_ROWS*XS_P + HD*W1T_P)*sizeof(float))   // 84096 B
#define PRE_ROWBLOCKS ((NB*NL + NB*NT)/PRE_ROWS)              // 140

__global__ void __launch_bounds__(PRE_THREADS)
precompute_kernel(const float* __restrict__ lig_s, const float* __restrict__ pro_s,
                  const float* __restrict__ W1,    const float* __restrict__ b1,
                  const float* __restrict__ bn_g,  const float* __restrict__ bn_b,
                  const float* __restrict__ bn_m,  const float* __restrict__ bn_v,
                  const float* __restrict__ W_pi,  const float* __restrict__ W_sig,
                  const float* __restrict__ W_mu)
{
    const int tid = threadIdx.x;

    // ---- W-fragment block (once per grid) ----
    if (blockIdx.x == PRE_ROWBLOCKS) {
        for (int idx = tid; idx < 1024; idx += PRE_THREADS) {
            int kc = idx >> 7, nc = (idx >> 5) & 3, ln = idx & 31;
            int n = nc*8 + (ln >> 2);
            int k = kc*16 + 2*(ln & 3);
            float w0 = wval(n, k,   W_pi, W_sig, W_mu);
            float w1 = wval(n, k+1, W_pi, W_sig, W_mu);
            float w8 = wval(n, k+8, W_pi, W_sig, W_mu);
            float w9 = wval(n, k+9, W_pi, W_sig, W_mu);
            g_Wfrag[idx] = make_uint2(cvt2h(w0, w1), cvt2h(w8, w9));
        }
        return;
    }

    extern __shared__ float sm[];
    float* Xs  = sm;                      // [32][129]
    float* W1t = sm + PRE_ROWS*XS_P;      // [128][132] transposed

    const int w    = tid >> 5;            // 0..15
    const int ln   = tid & 31;
    const int row0 = blockIdx.x * PRE_ROWS;
    const bool is_lig = (row0 < NB*NL);

    const float4* src = is_lig ? (const float4*)(lig_s + (size_t)row0*HD)
                               : (const float4*)(pro_s + (size_t)(row0 - NB*NL)*HD);
    #pragma unroll
    for (int i = 0; i < 2; i++) {
        int idx = tid + i*PRE_THREADS;    // < 1024
        float4 v = src[idx];
        int r = idx >> 5, c = (idx & 31) << 2;
        Xs[r*XS_P + c]   = v.x;
        Xs[r*XS_P + c+1] = v.y;
        Xs[r*XS_P + c+2] = v.z;
        Xs[r*XS_P + c+3] = v.w;
    }
    #pragma unroll
    for (int i = 0; i < (HD*HD)/PRE_THREADS; i++) {
        int idx = tid + i*PRE_THREADS;
        int h = idx >> 7, k = idx & (HD-1);
        W1t[k*W1T_P + h] = W1[idx];
    }
    __syncthreads();

    const int h0 = w << 3;
    const float* xrow = Xs + ln*XS_P;
    float acc[8];
    #pragma unroll
    for (int j = 0; j < 8; j++) acc[j] = 0.0f;

    #pragma unroll 4
    for (int k = 0; k < HD; k++) {
        float x = xrow[k];
        float4 wa = *(const float4*)(W1t + k*W1T_P + h0);      // uniform -> bcast
        float4 wb = *(const float4*)(W1t + k*W1T_P + h0 + 4);
        acc[0] = fmaf(x, wa.x, acc[0]);
        acc[1] = fmaf(x, wa.y, acc[1]);
        acc[2] = fmaf(x, wa.z, acc[2]);
        acc[3] = fmaf(x, wa.w, acc[3]);
        acc[4] = fmaf(x, wb.x, acc[4]);
        acc[5] = fmaf(x, wb.y, acc[5]);
        acc[6] = fmaf(x, wb.z, acc[6]);
        acc[7] = fmaf(x, wb.w, acc[7]);
    }

    const int row = row0 + ln;
    float o[8];
    if (is_lig) {
        #pragma unroll
        for (int j = 0; j < 8; j++) {
            int h = h0 + j;
            float s = bn_g[h] * rsqrtf(bn_v[h] + 1e-5f);
            o[j] = s * (acc[j] + b1[h] - bn_m[h]) + bn_b[h];
        }
        float4* dst = (float4*)(g_Al + (size_t)row*HD + h0);
        dst[0] = make_float4(o[0], o[1], o[2], o[3]);
        dst[1] = make_float4(o[4], o[5], o[6], o[7]);
    } else {
        #pragma unroll
        for (int j = 0; j < 8; j++) {
            int h = h0 + j;
            float s = bn_g[h] * rsqrtf(bn_v[h] + 1e-5f);
            o[j] = s * acc[j];
        }
        float4* dst = (float4*)(g_At + (size_t)(row - NB*NL)*HD + h0);
        dst[0] = make_float4(o[0], o[1], o[2], o[3]);
        dst[1] = make_float4(o[4], o[5], o[6], o[7]);
    }
}

// ---------------------------------------------------------------------------
// Pair kernel via mma.sync (HMMA fp16, single pass, fp32 accumulate).
// R13: block = 4 lig x 64 prot = 256 pairs, 512 threads (16 warps, warp =
// 1 lig x 16 prot). Grid 768. Per-block fixed cost amortized 2x vs R12.
// D buffer (256x34) exactly overlays At (64x136). Softmax without max-shift
// (logits ~N(0,0.8), overflow impossible).
// ---------------------------------------------------------------------------
#define THREADS 512
#define AT_P 136              // float pitch for At/Al staging (mod 32 == 8)

// smem float offsets — F_D overlaps F_AT (operands dead after mainloop)
#define F_AT   0              // 64 x 136 = 8704
#define F_AL   8704           // 4 x 136 = 544
#define F_W    9248           // [kc 8][nc 4][lane 32] uint2 = 2048 floats
#define F_D    0              // 256 x 34 = 8704  (union with F_AT)
#define F_BIAS 11296          // 32
#define F_PL   11328          // 4 x 4
#define F_PT   11344          // 64 x 4
#define SMF    11600          // floats -> 46400 bytes

__global__ void __launch_bounds__(THREADS, 2)
pair_kernel(const float* __restrict__ lig_pos, const float* __restrict__ pro_pos,
            const float* __restrict__ b_pi, const float* __restrict__ b_sig,
            const float* __restrict__ b_mu,
            float* __restrict__ out)
{
    extern __shared__ float sm[];
    const int tid  = threadIdx.x;
    const int w    = tid >> 5;           // 16 warps
    const int lane = tid & 31;
    const int r    = lane >> 2;          // 0..7
    const int q    = lane & 3;           // 0..3
    const int ligl = w >> 2;             // local ligand 0..3
    const int ph   = (w & 3) << 4;       // protein offset: 0,16,32,48
    const int b    = blockIdx.z;
    const int l0   = blockIdx.y * 4;
    const int t0   = blockIdx.x * 64;

    // ---- stage At (64 rows) and Al (4 rows), fp32, pitch 136 ----
    {
        const float4* src = (const float4*)(g_At + (size_t)(b*NT + t0)*HD);
        float4* dst = (float4*)&sm[F_AT];          // pitch 34 float4
        #pragma unroll
        for (int i = 0; i < 4; i++) {
            int idx = tid + i*THREADS;              // < 2048
            dst[(idx >> 5)*34 + (idx & 31)] = src[idx];
        }
    }
    if (tid < 128) {   // Al: 4 rows x 32 float4
        const float4* src = (const float4*)(g_Al + (size_t)(b*NL + l0)*HD);
        float4* dst = (float4*)&sm[F_AL];
        dst[(tid >> 5)*34 + (tid & 31)] = src[tid];
    }
    // ---- bulk-copy preconverted W fragments (8 KB, 1 uint4 per thread) ----
    ((uint4*)&sm[F_W])[tid] = ((const uint4*)g_Wfrag)[tid];
    if (tid < NG) {
        sm[F_BIAS + tid]      = b_pi[tid];
        sm[F_BIAS + 10 + tid] = b_sig[tid];
        sm[F_BIAS + 20 + tid] = b_mu[tid];
    }
    if (tid < 12) {
        int l = tid / 3, c = tid % 3;
        sm[F_PL + l*4 + c] = lig_pos[(size_t)(b*NL + l0 + l)*3 + c];
    }
    if (tid < 192) {
        int t = tid / 3, c = tid % 3;
        sm[F_PT + t*4 + c] = pro_pos[(size_t)(b*NT + t0 + t)*3 + c];
    }
    __syncthreads();

    // ---- mainloop: warp computes D[16 pairs][32 heads] ----
    float D[4][4];
    #pragma unroll
    for (int nc = 0; nc < 4; nc++)
        #pragma unroll
        for (int j = 0; j < 4; j++) D[nc][j] = 0.0f;

    const float* alr = &sm[F_AL + ligl*AT_P + 2*q];
    const float* atr = &sm[F_AT + (ph + r)*AT_P + 2*q];
    const uint2* wl2 = (const uint2*)&sm[F_W] + lane;

    #pragma unroll 2
    for (int kc = 0; kc < 8; kc++) {
        const int kb = kc*16;
        float2 L0 = *(const float2*)(alr + kb);
        float2 L8 = *(const float2*)(alr + kb + 8);
        uint32_t a[4];
        {
            float2 t00 = *(const float2*)(atr + kb);
            float2 t08 = *(const float2*)(atr + kb + 8);
            float2 t80 = *(const float2*)(atr + 8*AT_P + kb);
            float2 t88 = *(const float2*)(atr + 8*AT_P + kb + 8);
            a[0] = cvt2h(elu1(t00.x + L0.x), elu1(t00.y + L0.y));
            a[1] = cvt2h(elu1(t80.x + L0.x), elu1(t80.y + L0.y));
            a[2] = cvt2h(elu1(t08.x + L8.x), elu1(t08.y + L8.y));
            a[3] = cvt2h(elu1(t88.x + L8.x), elu1(t88.y + L8.y));
        }
        #pragma unroll
        for (int nc = 0; nc < 4; nc++) {
            uint2 wv = wl2[(kc*4 + nc)*32];
            uint32_t bb[2] = {wv.x, wv.y};
            mma_f16(D[nc], a, bb);
        }
    }

    // operands (At/Al/W) dead from here; D buffer overlaps them
    __syncthreads();

    // ---- D fragments -> smem (pair-major, pitch 34) ----
    {
        const int p = ligl*64 + ph + r;
        #pragma unroll
        for (int nc = 0; nc < 4; nc++) {
            *(float2*)&sm[F_D + p*34 + nc*8 + 2*q]     = make_float2(D[nc][0], D[nc][1]);
            *(float2*)&sm[F_D + (p+8)*34 + nc*8 + 2*q] = make_float2(D[nc][2], D[nc][3]);
        }
    }
    __syncthreads();

    // ---- split epilogue: tid<256 -> softmax+dist; tid>=256 -> sigma+mu ----
    {
        const int p  = tid & 255;
        const int ll = p >> 6, tl = p & 63;
        const float* row = &sm[F_D + p*34];
        const size_t pg = (size_t)((b*NL + l0 + ll)*NT) + t0 + tl;
        if (tid < 256) {
            float y[10];
            float ssum = 0.0f;
            #pragma unroll
            for (int g = 0; g < NG; g++) { y[g] = __expf(row[g] + sm[F_BIAS + g]); ssum += y[g]; }
            float inv = 1.0f / ssum;
            float2* po = (float2*)(out + OFF_PI + pg*NG);
            #pragma unroll
            for (int g = 0; g < 5; g++) po[g] = make_float2(y[2*g]*inv, y[2*g+1]*inv);
            float dx = sm[F_PL + ll*4]   - sm[F_PT + tl*4];
            float dy = sm[F_PL + ll*4+1] - sm[F_PT + tl*4+1];
            float dz = sm[F_PL + ll*4+2] - sm[F_PT + tl*4+2];
            out[OFF_D  + pg] = sqrtf(dx*dx + dy*dy + dz*dz);
            out[OFF_CB + pg] = (float)b;
        } else {
            float2* so = (float2*)(out + OFF_SIG + pg*NG);
            #pragma unroll
            for (int g = 0; g < 5; g++) {
                float s0 = elu1(row[10+2*g]   + sm[F_BIAS + 10 + 2*g])   + 1.1f;
                float s1 = elu1(row[10+2*g+1] + sm[F_BIAS + 10 + 2*g+1]) + 1.1f;
                so[g] = make_float2(s0, s1);
            }
            float2* mo = (float2*)(out + OFF_MU + pg*NG);
            #pragma unroll
            for (int g = 0; g < 5; g++) {
                float m0 = elu1(row[20+2*g]   + sm[F_BIAS + 20 + 2*g])   + 1.0f;
                float m1 = elu1(row[20+2*g+1] + sm[F_BIAS + 20 + 2*g+1]) + 1.0f;
                mo[g] = make_float2(m0, m1);
            }
        }
    }
}

// ---------------------------------------------------------------------------
extern "C" void kernel_launch(void* const* d_in, const int* in_sizes, int n_in,
                              void* d_out, int out_size)
{
    (void)in_sizes; (void)n_in; (void)out_size;
    const float* lig_s   = (const float*)d_in[0];
    const float* lig_pos = (const float*)d_in[1];
    const float* pro_s   = (const float*)d_in[3];
    const float* pro_pos = (const float*)d_in[4];
    const float* W1      = (const float*)d_in[6];
    const float* b1      = (const float*)d_in[7];
    const float* bn_g    = (const float*)d_in[8];
    const float* bn_b    = (const float*)d_in[9];
    const float* bn_m    = (const float*)d_in[10];
    const float* bn_v    = (const float*)d_in[11];
    const float* W_pi    = (const float*)d_in[12];
    const float* b_pi    = (const float*)d_in[13];
    const float* W_sig   = (const float*)d_in[14];
    const float* b_sig   = (const float*)d_in[15];
    const float* W_mu    = (const float*)d_in[16];
    const float* b_mu    = (const float*)d_in[17];
    float* out = (float*)d_out;

    cudaFuncSetAttribute(precompute_kernel,
                         cudaFuncAttributeMaxDynamicSharedMemorySize, (int)PRE_SMEM);
    precompute_kernel<<<PRE_ROWBLOCKS + 1, PRE_THREADS, PRE_SMEM>>>(
        lig_s, pro_s, W1, b1, bn_g, bn_b, bn_m, bn_v, W_pi, W_sig, W_mu);

    cudaFuncSetAttribute(pair_kernel,
                         cudaFuncAttributeMaxDynamicSharedMemorySize, SMF*(int)sizeof(float));
    pair_kernel<<<dim3(NT/64, NL/4, NB), THREADS, SMF*sizeof(float)>>>(
        lig_pos, pro_pos, b_pi, b_sig, b_mu, out);
}

// round 14
// speedup vs baseline: 1.2899x; 1.2899x over previous
#include <cuda_runtime.h>
#include <cuda_fp16.h>
#include <math.h>
#include <stdint.h>

#define NB 8
#define NL 48
#define NT 512
#define HD 128
#define NG 10
#define M_TOTAL (NB*NL*NT)          // 196608

#define OFF_PI  0
#define OFF_SIG (M_TOTAL*NG)
#define OFF_MU  (2*M_TOTAL*NG)
#define OFF_D   (3*M_TOTAL*NG)
#define OFF_CB  (3*M_TOTAL*NG + M_TOTAL)

// scratch (device globals: no allocation)
__device__ float g_Al[NB*NL*HD];    // 384 x 128
__device__ float g_At[NB*NT*HD];    // 4096 x 128
__device__ uint2 g_Wfrag[1024];     // fp16 W fragments [kc 8][nc 4][lane 32]
__device__ float4 g_Plig[NB*NL];    // padded ligand positions
__device__ float4 g_Ppro[NB*NT];    // padded protein positions

__device__ __forceinline__ float elu1(float x) {
    return x > 0.0f ? x : (__expf(x) - 1.0f);
}

// pack two fp32 into f16x2: {lo16 = e0, hi16 = e1}
__device__ __forceinline__ uint32_t cvt2h(float e0, float e1) {
    uint32_t r;
    asm("cvt.rn.f16x2.f32 %0, %1, %2;" : "=r"(r) : "f"(e1), "f"(e0));
    return r;
}

// warp-level fp16 MMA, d += a*b, fp32 accumulate (baseline PTX sm_80+)
__device__ __forceinline__ void mma_f16(float* d, const uint32_t* a, const uint32_t* b) {
    asm volatile("mma.sync.aligned.m16n8k16.row.col.f32.f16.f16.f32 "
        "{%0,%1,%2,%3}, {%4,%5,%6,%7}, {%8,%9}, {%0,%1,%2,%3};"
        : "+f"(d[0]), "+f"(d[1]), "+f"(d[2]), "+f"(d[3])
        : "r"(a[0]), "r"(a[1]), "r"(a[2]), "r"(a[3]), "r"(b[0]), "r"(b[1]));
}

__device__ __forceinline__ float wval(int n, int k, const float* __restrict__ wp,
                                      const float* __restrict__ ws,
                                      const float* __restrict__ wm) {
    if (n < 10) return wp[n*HD + k];
    if (n < 20) return ws[(n-10)*HD + k];
    if (n < 30) return wm[(n-20)*HD + k];
    return 0.0f;
}

// ---------------------------------------------------------------------------
// Precompute: A_l = s*(lig_s@W1^T + b1 - mean) + beta ;  A_t = s*(pro_s@W1^T)
// Last block additionally: fp16 W fragments + padded float4 positions.
// ---------------------------------------------------------------------------
#define PRE_ROWS 32
#define PRE_THREADS 512
#define XS_P  129
#define W1T_P 132
#define PRE_SMEM ((PRE_ROWS*XS_P + HD*W1T_P)*sizeof(float))   // 84096 B
#define PRE_ROWBLOCKS ((NB*NL + NB*NT)/PRE_ROWS)              // 140

__global__ void __launch_bounds__(PRE_THREADS)
precompute_kernel(const float* __restrict__ lig_s, const float* __restrict__ pro_s,
                  const float* __restrict__ W1,    const float* __restrict__ b1,
                  const float* __restrict__ bn_g,  const float* __restrict__ bn_b,
                  const float* __restrict__ bn_m,  const float* __restrict__ bn_v,
                  const float* __restrict__ W_pi,  const float* __restrict__ W_sig,
                  const float* __restrict__ W_mu,
                  const float* __restrict__ lig_pos, const float* __restrict__ pro_pos)
{
    const int tid = threadIdx.x;

    // ---- W-fragment + position-padding block (once per grid) ----
    if (blockIdx.x == PRE_ROWBLOCKS) {
        for (int idx = tid; idx < 1024; idx += PRE_THREADS) {
            int kc = idx >> 7, nc = (idx >> 5) & 3, ln = idx & 31;
            int n = nc*8 + (ln >> 2);
            int k = kc*16 + 2*(ln & 3);
            float w0 = wval(n, k,   W_pi, W_sig, W_mu);
            float w1 = wval(n, k+1, W_pi, W_sig, W_mu);
            float w8 = wval(n, k+8, W_pi, W_sig, W_mu);
            float w9 = wval(n, k+9, W_pi, W_sig, W_mu);
            g_Wfrag[idx] = make_uint2(cvt2h(w0, w1), cvt2h(w8, w9));
        }
        if (tid < NB*NL)
            g_Plig[tid] = make_float4(lig_pos[tid*3], lig_pos[tid*3+1], lig_pos[tid*3+2], 0.0f);
        for (int i = tid; i < NB*NT; i += PRE_THREADS)
            g_Ppro[i] = make_float4(pro_pos[i*3], pro_pos[i*3+1], pro_pos[i*3+2], 0.0f);
        return;
    }

    extern __shared__ float sm[];
    float* Xs  = sm;                      // [32][129]
    float* W1t = sm + PRE_ROWS*XS_P;      // [128][132] transposed

    const int w    = tid >> 5;            // 0..15
    const int ln   = tid & 31;
    const int row0 = blockIdx.x * PRE_ROWS;
    const bool is_lig = (row0 < NB*NL);

    const float4* src = is_lig ? (const float4*)(lig_s + (size_t)row0*HD)
                               : (const float4*)(pro_s + (size_t)(row0 - NB*NL)*HD);
    #pragma unroll
    for (int i = 0; i < 2; i++) {
        int idx = tid + i*PRE_THREADS;    // < 1024
        float4 v = src[idx];
        int r = idx >> 5, c = (idx & 31) << 2;
        Xs[r*XS_P + c]   = v.x;
        Xs[r*XS_P + c+1] = v.y;
        Xs[r*XS_P + c+2] = v.z;
        Xs[r*XS_P + c+3] = v.w;
    }
    #pragma unroll
    for (int i = 0; i < (HD*HD)/PRE_THREADS; i++) {
        int idx = tid + i*PRE_THREADS;
        int h = idx >> 7, k = idx & (HD-1);
        W1t[k*W1T_P + h] = W1[idx];
    }
    __syncthreads();

    const int h0 = w << 3;
    const float* xrow = Xs + ln*XS_P;
    float acc[8];
    #pragma unroll
    for (int j = 0; j < 8; j++) acc[j] = 0.0f;

    #pragma unroll 4
    for (int k = 0; k < HD; k++) {
        float x = xrow[k];
        float4 wa = *(const float4*)(W1t + k*W1T_P + h0);      // uniform -> bcast
        float4 wb = *(const float4*)(W1t + k*W1T_P + h0 + 4);
        acc[0] = fmaf(x, wa.x, acc[0]);
        acc[1] = fmaf(x, wa.y, acc[1]);
        acc[2] = fmaf(x, wa.z, acc[2]);
        acc[3] = fmaf(x, wa.w, acc[3]);
        acc[4] = fmaf(x, wb.x, acc[4]);
        acc[5] = fmaf(x, wb.y, acc[5]);
        acc[6] = fmaf(x, wb.z, acc[6]);
        acc[7] = fmaf(x, wb.w, acc[7]);
    }

    const int row = row0 + ln;
    float o[8];
    if (is_lig) {
        #pragma unroll
        for (int j = 0; j < 8; j++) {
            int h = h0 + j;
            float s = bn_g[h] * rsqrtf(bn_v[h] + 1e-5f);
            o[j] = s * (acc[j] + b1[h] - bn_m[h]) + bn_b[h];
        }
        float4* dst = (float4*)(g_Al + (size_t)row*HD + h0);
        dst[0] = make_float4(o[0], o[1], o[2], o[3]);
        dst[1] = make_float4(o[4], o[5], o[6], o[7]);
    } else {
        #pragma unroll
        for (int j = 0; j < 8; j++) {
            int h = h0 + j;
            float s = bn_g[h] * rsqrtf(bn_v[h] + 1e-5f);
            o[j] = s * acc[j];
        }
        float4* dst = (float4*)(g_At + (size_t)(row - NB*NL)*HD + h0);
        dst[0] = make_float4(o[0], o[1], o[2], o[3]);
        dst[1] = make_float4(o[4], o[5], o[6], o[7]);
    }
}

// ---------------------------------------------------------------------------
// Pair kernel via mma.sync (HMMA fp16, single pass, fp32 accumulate).
// R14: exact R12 shape (256 thr, 48 regs, 5 blocks/SM, 128 pairs/block) +
// no-max softmax + float4 position staging (no div/mod prologue).
// ---------------------------------------------------------------------------
#define THREADS 256
#define AT_P 136              // float pitch for At/Al staging (mod 32 == 8)

// smem float offsets — F_D overlaps [F_AT..) (operands dead after mainloop)
#define F_AT   0              // 32 x 136 = 4352
#define F_AL   4352           // 4 x 136 = 544
#define F_W    4896           // [kc 8][nc 4][lane 32] uint2 = 2048 floats
#define F_D    0              // 128 x 34 = 4352  (union)
#define F_BIAS 6944           // 32
#define F_PL   6976           // 4 x 4
#define F_PT   6992           // 32 x 4
#define SMF    7120           // floats -> 28480 bytes

__global__ void __launch_bounds__(THREADS, 5)
pair_kernel(const float* __restrict__ b_pi, const float* __restrict__ b_sig,
            const float* __restrict__ b_mu,
            float* __restrict__ out)
{
    extern __shared__ float sm[];
    const int tid  = threadIdx.x;
    const int w    = tid >> 5;           // 8 warps
    const int lane = tid & 31;
    const int r    = lane >> 2;          // 0..7
    const int q    = lane & 3;           // 0..3
    const int ligl = w >> 1;             // local ligand 0..3
    const int ph   = (w & 1) << 4;       // protein half offset: 0 or 16
    const int b    = blockIdx.z;
    const int l0   = blockIdx.y * 4;
    const int t0   = blockIdx.x * 32;

    // ---- stage At (32 rows) and Al (4 rows), fp32, pitch 136 ----
    {
        const float4* src = (const float4*)(g_At + (size_t)(b*NT + t0)*HD);
        float4* dst = (float4*)&sm[F_AT];          // pitch 34 float4
        #pragma unroll
        for (int i = 0; i < 4; i++) {
            int idx = tid + i*THREADS;              // < 1024
            dst[(idx >> 5)*34 + (idx & 31)] = src[idx];
        }
    }
    if (tid < 128) {   // Al: 4 rows x 32 float4
        const float4* src = (const float4*)(g_Al + (size_t)(b*NL + l0)*HD);
        float4* dst = (float4*)&sm[F_AL];
        dst[(tid >> 5)*34 + (tid & 31)] = src[tid];
    }
    // ---- bulk-copy preconverted W fragments (8 KB) ----
    {
        const uint4* src4 = (const uint4*)g_Wfrag;   // 512 uint4
        uint4* dst4 = (uint4*)&sm[F_W];
        dst4[tid]       = src4[tid];
        dst4[tid + 256] = src4[tid + 256];
    }
    if (tid < NG) {
        sm[F_BIAS + tid]      = b_pi[tid];
        sm[F_BIAS + 10 + tid] = b_sig[tid];
        sm[F_BIAS + 20 + tid] = b_mu[tid];
    }
    if (tid < 4)
        ((float4*)&sm[F_PL])[tid] = g_Plig[b*NL + l0 + tid];
    if (tid < 32)
        ((float4*)&sm[F_PT])[tid] = g_Ppro[b*NT + t0 + tid];
    __syncthreads();

    // ---- mainloop: warp computes D[16 pairs][32 heads] ----
    float D[4][4];
    #pragma unroll
    for (int nc = 0; nc < 4; nc++)
        #pragma unroll
        for (int j = 0; j < 4; j++) D[nc][j] = 0.0f;

    const float* alr = &sm[F_AL + ligl*AT_P + 2*q];
    const float* atr = &sm[F_AT + (ph + r)*AT_P + 2*q];
    const uint2* wl2 = (const uint2*)&sm[F_W] + lane;

    #pragma unroll 2
    for (int kc = 0; kc < 8; kc++) {
        const int kb = kc*16;
        float2 L0 = *(const float2*)(alr + kb);
        float2 L8 = *(const float2*)(alr + kb + 8);
        uint32_t a[4];
        {
            float2 t00 = *(const float2*)(atr + kb);
            float2 t08 = *(const float2*)(atr + kb + 8);
            float2 t80 = *(const float2*)(atr + 8*AT_P + kb);
            float2 t88 = *(const float2*)(atr + 8*AT_P + kb + 8);
            a[0] = cvt2h(elu1(t00.x + L0.x), elu1(t00.y + L0.y));
            a[1] = cvt2h(elu1(t80.x + L0.x), elu1(t80.y + L0.y));
            a[2] = cvt2h(elu1(t08.x + L8.x), elu1(t08.y + L8.y));
            a[3] = cvt2h(elu1(t88.x + L8.x), elu1(t88.y + L8.y));
        }
        #pragma unroll
        for (int nc = 0; nc < 4; nc++) {
            uint2 wv = wl2[(kc*4 + nc)*32];
            uint32_t bb[2] = {wv.x, wv.y};
            mma_f16(D[nc], a, bb);
        }
    }

    // operands (At/Al/W) dead from here; D buffer overlaps them
    __syncthreads();

    // ---- D fragments -> smem (pair-major, pitch 34) ----
    {
        const int p = ligl*32 + ph + r;
        #pragma unroll
        for (int nc = 0; nc < 4; nc++) {
            *(float2*)&sm[F_D + p*34 + nc*8 + 2*q]     = make_float2(D[nc][0], D[nc][1]);
            *(float2*)&sm[F_D + (p+8)*34 + nc*8 + 2*q] = make_float2(D[nc][2], D[nc][3]);
        }
    }
    __syncthreads();

    // ---- split epilogue: tid<128 -> softmax+dist; tid>=128 -> sigma+mu ----
    {
        const int p  = tid & 127;
        const int ll = p >> 5, tl = p & 31;
        const float* row = &sm[F_D + p*34];
        const size_t pg = (size_t)((b*NL + l0 + ll)*NT) + t0 + tl;
        if (tid < 128) {
            float y[10];
            float ssum = 0.0f;
            #pragma unroll
            for (int g = 0; g < NG; g++) { y[g] = __expf(row[g] + sm[F_BIAS + g]); ssum += y[g]; }
            float inv = 1.0f / ssum;
            float2* po = (float2*)(out + OFF_PI + pg*NG);
            #pragma unroll
            for (int g = 0; g < 5; g++) po[g] = make_float2(y[2*g]*inv, y[2*g+1]*inv);
            float dx = sm[F_PL + ll*4]   - sm[F_PT + tl*4];
            float dy = sm[F_PL + ll*4+1] - sm[F_PT + tl*4+1];
            float dz = sm[F_PL + ll*4+2] - sm[F_PT + tl*4+2];
            out[OFF_D  + pg] = sqrtf(dx*dx + dy*dy + dz*dz);
            out[OFF_CB + pg] = (float)b;
        } else {
            float2* so = (float2*)(out + OFF_SIG + pg*NG);
            #pragma unroll
            for (int g = 0; g < 5; g++) {
                float s0 = elu1(row[10+2*g]   + sm[F_BIAS + 10 + 2*g])   + 1.1f;
                float s1 = elu1(row[10+2*g+1] + sm[F_BIAS + 10 + 2*g+1]) + 1.1f;
                so[g] = make_float2(s0, s1);
            }
            float2* mo = (float2*)(out + OFF_MU + pg*NG);
            #pragma unroll
            for (int g = 0; g < 5; g++) {
                float m0 = elu1(row[20+2*g]   + sm[F_BIAS + 20 + 2*g])   + 1.0f;
                float m1 = elu1(row[20+2*g+1] + sm[F_BIAS + 20 + 2*g+1]) + 1.0f;
                mo[g] = make_float2(m0, m1);
            }
        }
    }
}

// ---------------------------------------------------------------------------
extern "C" void kernel_launch(void* const* d_in, const int* in_sizes, int n_in,
                              void* d_out, int out_size)
{
    (void)in_sizes; (void)n_in; (void)out_size;
    const float* lig_s   = (const float*)d_in[0];
    const float* lig_pos = (const float*)d_in[1];
    const float* pro_s   = (const float*)d_in[3];
    const float* pro_pos = (const float*)d_in[4];
    const float* W1      = (const float*)d_in[6];
    const float* b1      = (const float*)d_in[7];
    const float* bn_g    = (const float*)d_in[8];
    const float* bn_b    = (const float*)d_in[9];
    const float* bn_m    = (const float*)d_in[10];
    const float* bn_v    = (const float*)d_in[11];
    const float* W_pi    = (const float*)d_in[12];
    const float* b_pi    = (const float*)d_in[13];
    const float* W_sig   = (const float*)d_in[14];
    const float* b_sig   = (const float*)d_in[15];
    const float* W_mu    = (const float*)d_in[16];
    const float* b_mu    = (const float*)d_in[17];
    float* out = (float*)d_out;

    cudaFuncSetAttribute(precompute_kernel,
                         cudaFuncAttributeMaxDynamicSharedMemorySize, (int)PRE_SMEM);
    precompute_kernel<<<PRE_ROWBLOCKS + 1, PRE_THREADS, PRE_SMEM>>>(
        lig_s, pro_s, W1, b1, bn_g, bn_b, bn_m, bn_v, W_pi, W_sig, W_mu,
        lig_pos, pro_pos);

    pair_kernel<<<dim3(NT/32, NL/4, NB), THREADS, SMF*sizeof(float)>>>(
        b_pi, b_sig, b_mu, out);
}